// round 14
// baseline (speedup 1.0000x reference)
#include <cuda_runtime.h>
#include <math.h>

#define BLOCK 32
#define NSH 81   // sum(2l+1), l=0..8

// FINAL — confirmed 3x at 49.6-50.1 us (R7/R10/R13).
// Real spherical harmonics (e3nn SphericalHarmonicsAlphaBeta, l=0..8, mul=1):
//   out[n, l*l + l + m] = P̄_{l,|m|}(cos b) * sin(b)^|m| * A_m(a)
//   A_m = 1 (m=0), sqrt(2)*cos(m a) (m>0), sqrt(2)*sin(|m| a) (m<0)
// P̄ via stable fully-normalized ALF recurrences (no Condon-Shortley phase);
// rel_err 2.2e-6 vs the reference polynomial expansion.
// Design: one warp per CTA; 32-point tile staged in 10.1 KB smem
// (stride-81 rows, 81 odd -> bank-conflict-free); flushed as coalesced
// float4 evict-first (.cs) streaming stores.
// Design-space map (all falsified slower — do not revisit):
//  - store policy: default-WB +7us, .wt +7us (inter-replay L2 flush
//    interference; invisible to ncu -c 1). .cs uniquely fast.
//  - input loads: .cs +7us (L2-resident inputs across replays matter).
//  - 256-bit st.global.cs.v8: regresses at 90 regs (R6) AND 48 regs (R12)
//    — splits to 2 LSU wavefronts anyway, serializes store chain.
//  - TMA bulk store (R3): same L1 path, blocks CTA retirement.
//  - persistent grid (R5): serializes per-warp compute/store phases, -9.5us.
//  - BLOCK 64/128, CTA-barrier variants: equal or slower.
//  - occupancy 21%->29%: DRAM% invariant (not occupancy-limited).
// 332 MB @ ~6.7 TB/s timed ≈ 84% of spec HBM write bandwidth — at the
// streaming-write floor for this access pattern on sm_103a.
__global__ __launch_bounds__(BLOCK)
void sh_ab_kernel(const float* __restrict__ alpha,
                  const float* __restrict__ beta,
                  float* __restrict__ out, int n)
{
    __shared__ __align__(16) float tile[BLOCK * NSH];   // 10368 B

    const int lane = threadIdx.x;
    const int point = blockIdx.x * BLOCK + lane;

    float a = 0.f, b = 0.f;
    if (point < n) { a = alpha[point]; b = beta[point]; }

    float sa, ca, sb, cb;
    __sincosf(a, &sa, &ca);
    __sincosf(b, &sb, &cb);
    const float z = cb;   // polynomial variable
    const float y = sb;   // sin(beta) >= 0 on [0, pi]

    // cos(m a), sin(m a) for m=0..8 via Chebyshev recurrence
    float cm[9], sn[9];
    cm[0] = 1.f; sn[0] = 0.f;
    cm[1] = ca;  sn[1] = sa;
    const float t2 = 2.f * ca;
#pragma unroll
    for (int m = 2; m <= 8; ++m) {
        cm[m] = t2 * cm[m-1] - cm[m-2];
        sn[m] = t2 * sn[m-1] - sn[m-2];
    }

    const float SQ2 = 1.41421356237309515f;
    float* row = &tile[lane * NSH];

    // m-major sweep: tiny live register set per column
    float pmm = 0.28209479177387814f;   // P̄_00 = sqrt(1/4pi)
#pragma unroll
    for (int m = 0; m <= 8; ++m) {
        if (m > 0)
            pmm *= sqrtf((2.f*m + 1.f) / (2.f*m)) * y;   // sectoral step

        const float Ac = (m == 0) ? 1.f : SQ2 * cm[m];
        const float As = SQ2 * sn[m];

        // l = m
        float plm2 = pmm;
        {
            const int l = m;
            row[l*l + l + m] = plm2 * Ac;
            if (m > 0) row[l*l + l - m] = plm2 * As;
        }
        if (m < 8) {
            // l = m+1
            float plm1 = sqrtf(2.f*m + 3.f) * z * pmm;
            {
                const int l = m + 1;
                row[l*l + l + m] = plm1 * Ac;
                if (m > 0) row[l*l + l - m] = plm1 * As;
            }
            // l = m+2 .. 8
#pragma unroll
            for (int l = m + 2; l <= 8; ++l) {
                const float al = sqrtf((4.f*l*l - 1.f) / (float)(l*l - m*m));
                const float bl = sqrtf((float)((l-1)*(l-1) - m*m) /
                                       (4.f*(l-1)*(l-1) - 1.f));
                const float pl = al * (z * plm1 - bl * plm2);
                row[l*l + l + m] = pl * Ac;
                if (m > 0) row[l*l + l - m] = pl * As;
                plm2 = plm1; plm1 = pl;
            }
        }
    }

    __syncwarp();

    // Coalesced streaming writeback: 32*81 floats = 648 float4
    const long long base = (long long)blockIdx.x * (BLOCK * NSH);
    const int remaining = n - blockIdx.x * BLOCK;
    if (remaining >= BLOCK) {
        float4* dst = reinterpret_cast<float4*>(out + base);
        const float4* src = reinterpret_cast<const float4*>(tile);
#pragma unroll 5
        for (int i = lane; i < (BLOCK * NSH) / 4; i += BLOCK)
            __stcs(&dst[i], src[i]);
    } else {
        const int floats = (remaining > 0 ? remaining : 0) * NSH;
        for (int i = lane; i < floats; i += BLOCK)
            __stcs(&out[base + i], tile[i]);
    }
}

extern "C" void kernel_launch(void* const* d_in, const int* in_sizes, int n_in,
                              void* d_out, int out_size)
{
    const float* alpha = (const float*)d_in[0];
    const float* beta  = (const float*)d_in[1];
    float* out = (float*)d_out;
    const int n = in_sizes[0];
    const int grid = (n + BLOCK - 1) / BLOCK;
    sh_ab_kernel<<<grid, BLOCK>>>(alpha, beta, out, n);
}